// round 7
// baseline (speedup 1.0000x reference)
#include <cuda_runtime.h>
#include <cuda_fp16.h>
#include <cstdint>

#define NN   100000
#define HD   64
#define EMAX 3200000
#define NBLK ((NN + 1023) / 1024)   // 98
#define MBLK ((NN + 63) / 64)       // 1563

// ---- scratch (device globals; no allocation allowed) ----
__device__ __align__(16) float  g_h[NN * HD];        // node features fp32 (25.6 MB)
__device__ __align__(16) __half g_h16[2][NN * HD];   // fp16 gather mirrors, ping-pong (2x12.8 MB)
__device__ int   g_cnt[NN];
__device__ float g_inv[NN];
__device__ int   g_rowptr[NN + 1];
__device__ int   g_fill[NN];
__device__ int   g_esrc[EMAX];
__device__ int   g_is64;
__device__ int   g_bsum[NBLK];
__device__ int   g_boff[NBLK];

// ---------------------------------------------------------------- mma helpers
__device__ __forceinline__ uint32_t cvt_tf32(float x) {
    uint32_t r; asm("cvt.rna.tf32.f32 %0, %1;" : "=r"(r) : "f"(x)); return r;
}
__device__ __forceinline__ void split_tf32(float x, uint32_t& hi, uint32_t& lo) {
    hi = cvt_tf32(x);
    lo = cvt_tf32(x - __uint_as_float(hi));
}
__device__ __forceinline__ void mma_tf32(float* d, const uint32_t* a, const uint32_t* b) {
    asm volatile(
        "mma.sync.aligned.m16n8k8.row.col.f32.tf32.tf32.f32 "
        "{%0,%1,%2,%3}, {%4,%5,%6,%7}, {%8,%9}, {%0,%1,%2,%3};\n"
        : "+f"(d[0]), "+f"(d[1]), "+f"(d[2]), "+f"(d[3])
        : "r"(a[0]), "r"(a[1]), "r"(a[2]), "r"(a[3]), "r"(b[0]), "r"(b[1]));
}

// ---------------------------------------------------------------- dtype probe
__global__ void detect_kernel(const int* __restrict__ ei32) {
    if (threadIdx.x == 0 && blockIdx.x == 0) {
        int nz = 0;
        for (int k = 0; k < 64; k++) nz |= ei32[2 * k + 1];
        g_is64 = (nz == 0) ? 1 : 0;
    }
}
__device__ __forceinline__ int load_idx(const void* ei, size_t pos) {
    if (g_is64) return (int)((const long long*)ei)[pos];
    return ((const int*)ei)[pos];
}

// ---------------------------------------------------------------- zero / degree
__global__ void zero_kernel() {
    int i = blockIdx.x * blockDim.x + threadIdx.x;
    if (i < NN) { g_cnt[i] = 0; g_fill[i] = 0; }
}
__global__ void degree_kernel(const void* __restrict__ ei, int E) {
    int e = blockIdx.x * blockDim.x + threadIdx.x;
    if (e < E) {
        int d = load_idx(ei, (size_t)E + e);
        if ((unsigned)d < NN) atomicAdd(&g_cnt[d], 1);
    }
}

// ---------------------------------------------------------------- hierarchical scan
__global__ __launch_bounds__(1024) void scan_partial_kernel() {
    __shared__ int s[1024];
    int tid = threadIdx.x, b = blockIdx.x;
    int i = b * 1024 + tid;
    int v = (i < NN) ? g_cnt[i] : 0;
    if (i < NN) g_inv[i] = 1.0f / fmaxf((float)v, 1.0f);
    s[tid] = v;
    __syncthreads();
#pragma unroll
    for (int off = 1; off < 1024; off <<= 1) {
        int t = (tid >= off) ? s[tid - off] : 0;
        __syncthreads();
        s[tid] += t;
        __syncthreads();
    }
    if (i < NN) g_rowptr[i + 1] = s[tid];
    if (tid == 1023) g_bsum[b] = s[1023];
    if (i == 0) g_rowptr[0] = 0;
}
__global__ void scan_bsum_kernel() {
    __shared__ int s[128];
    int tid = threadIdx.x;
    int v = (tid < NBLK) ? g_bsum[tid] : 0;
    s[tid] = v;
    __syncthreads();
#pragma unroll
    for (int off = 1; off < 128; off <<= 1) {
        int t = (tid >= off) ? s[tid - off] : 0;
        __syncthreads();
        s[tid] += t;
        __syncthreads();
    }
    if (tid < NBLK) g_boff[tid] = s[tid] - v;
}
__global__ __launch_bounds__(1024) void scan_add_kernel() {
    int i = blockIdx.x * 1024 + threadIdx.x;
    if (i < NN) g_rowptr[i + 1] += g_boff[blockIdx.x];
}

// ---------------------------------------------------------------- counting-sort scatter
__global__ void scatter_kernel(const void* __restrict__ ei, int E) {
    int e = blockIdx.x * blockDim.x + threadIdx.x;
    if (e < E) {
        int srcv = load_idx(ei, (size_t)e);
        int d    = load_idx(ei, (size_t)E + e);
        if ((unsigned)d < NN && (unsigned)srcv < NN) {
            int pos = g_rowptr[d] + atomicAdd(&g_fill[d], 1);
            if ((unsigned)pos < EMAX) g_esrc[pos] = srcv;
        }
    }
}

// ================================================================ MMA GEMMs
#define AW 68
#define BW 72

__device__ __forceinline__ void mma_kstep(const float* As, const float* Bs,
                                          int m0, int n0, int k0,
                                          int qrow, int qcol,
                                          float acc[4][4]) {
    float af[4];
    af[0] = As[(m0 + qrow) * AW + k0 + qcol];
    af[1] = As[(m0 + qrow + 8) * AW + k0 + qcol];
    af[2] = As[(m0 + qrow) * AW + k0 + qcol + 4];
    af[3] = As[(m0 + qrow + 8) * AW + k0 + qcol + 4];
    uint32_t ah[4], al[4];
#pragma unroll
    for (int i = 0; i < 4; i++) split_tf32(af[i], ah[i], al[i]);
#pragma unroll
    for (int nt = 0; nt < 4; nt++) {
        int nn = n0 + nt * 8;
        float bf0 = Bs[(k0 + qcol) * BW + nn + qrow];
        float bf1 = Bs[(k0 + qcol + 4) * BW + nn + qrow];
        uint32_t bh[2], blo[2];
        split_tf32(bf0, bh[0], blo[0]);
        split_tf32(bf1, bh[1], blo[1]);
        mma_tf32(acc[nt], ah, bh);
        mma_tf32(acc[nt], ah, blo);
        mma_tf32(acc[nt], al, bh);
    }
}

// ---------------------------------------------------------------- input GEMM: h = x @ Win + b_in
__global__ __launch_bounds__(256) void gemm_in_mma(const float* __restrict__ x,
                                                   const float* __restrict__ Win,
                                                   const float* __restrict__ bin) {
    __shared__ __align__(16) float As[64 * AW];
    __shared__ __align__(16) float Bs[64 * BW];
    int tid = threadIdx.x;
    int wid = tid >> 5, lane = tid & 31;
    int warpM = wid & 3, warpN = wid >> 2;
    int qrow = lane >> 2, qcol = lane & 3;
    int row0 = blockIdx.x * 64;
    float acc[4][4];
#pragma unroll
    for (int nt = 0; nt < 4; nt++)
#pragma unroll
        for (int i = 0; i < 4; i++) acc[nt][i] = 0.f;

    for (int kc = 0; kc < 512; kc += 64) {
#pragma unroll
        for (int it = 0; it < 4; it++) {
            int idx = tid + it * 256;
            int r = idx >> 4, c4 = idx & 15;
            int grow = row0 + r;
            float4 v = make_float4(0.f, 0.f, 0.f, 0.f);
            if (grow < NN) v = *(const float4*)(x + (size_t)grow * 512 + kc + c4 * 4);
            *(float4*)&As[r * AW + c4 * 4] = v;
            *(float4*)&Bs[r * BW + c4 * 4] = *(const float4*)(Win + (size_t)(kc + r) * 64 + c4 * 4);
        }
        __syncthreads();
#pragma unroll
        for (int kk = 0; kk < 8; kk++)
            mma_kstep(As, Bs, warpM * 16, warpN * 32, kk * 8, qrow, qcol, acc);
        __syncthreads();
    }
#pragma unroll
    for (int nt = 0; nt < 4; nt++) {
        int gc = warpN * 32 + nt * 8 + qcol * 2;
        float2 bv = *(const float2*)(bin + gc);
#pragma unroll
        for (int half = 0; half < 2; half++) {
            int gr = row0 + warpM * 16 + qrow + half * 8;
            if (gr < NN) {
                float2 o;
                o.x = acc[nt][half * 2 + 0] + bv.x;
                o.y = acc[nt][half * 2 + 1] + bv.y;
                *(float2*)(g_h + (size_t)gr * 64 + gc) = o;
                *(__half2*)(&g_h16[0][(size_t)gr * 64 + gc]) = __floats2half2_rn(o.x, o.y);
            }
        }
    }
}

// ---------------------------------------------------------------- FUSED layer:
// aggregate 64 nodes (warp=8 nodes) from g_h16[buf] into smem As, mma with Wl,
// then As = h rows, mma with Wr; epilogue h += relu(conv + bl), write g_h16[buf^1].
__global__ __launch_bounds__(256) void layer_fused_kernel(const float* __restrict__ Wl,
                                                          const float* __restrict__ Wr,
                                                          const float* __restrict__ bl,
                                                          int buf) {
    __shared__ __align__(16) float As[64 * AW];
    __shared__ __align__(16) float Bs[64 * BW];
    int tid = threadIdx.x;
    int wid = tid >> 5, lane = tid & 31;
    int warpM = wid & 3, warpN = wid >> 2;
    int qrow = lane >> 2, qcol = lane & 3;
    int row0 = blockIdx.x * 64;
    float acc[4][4];
#pragma unroll
    for (int nt = 0; nt < 4; nt++)
#pragma unroll
        for (int i = 0; i < 4; i++) acc[nt][i] = 0.f;

    // ---- load Bs = Wl
#pragma unroll
    for (int it = 0; it < 4; it++) {
        int idx = tid + it * 256;
        int r = idx >> 4, c4 = idx & 15;
        *(float4*)&Bs[r * BW + c4 * 4] = *(const float4*)(Wl + (size_t)r * 64 + c4 * 4);
    }

    // ---- phase A: aggregate 8 nodes per warp into As rows (reads OLD buffer)
    const __half2* __restrict__ base = (const __half2*)g_h16[buf];
#pragma unroll 1
    for (int q = 0; q < 8; q++) {
        int lr = wid * 8 + q;
        int node = row0 + lr;
        float2 a0 = make_float2(0.f, 0.f), a1 = a0, a2 = a0, a3 = a0;
        if (node < NN) {
            int beg = g_rowptr[node], end = g_rowptr[node + 1];
            int n = end - beg;
            int nfull = n & ~31;
            int j = beg;
            for (; j < beg + nfull; j += 32) {
                int sidx = g_esrc[j + lane];
#pragma unroll
                for (int t = 0; t < 32; t += 4) {
                    int s0 = __shfl_sync(0xffffffffu, sidx, t + 0);
                    int s1 = __shfl_sync(0xffffffffu, sidx, t + 1);
                    int s2 = __shfl_sync(0xffffffffu, sidx, t + 2);
                    int s3 = __shfl_sync(0xffffffffu, sidx, t + 3);
                    float2 v0 = __half22float2(base[(size_t)s0 * 32 + lane]);
                    float2 v1 = __half22float2(base[(size_t)s1 * 32 + lane]);
                    float2 v2 = __half22float2(base[(size_t)s2 * 32 + lane]);
                    float2 v3 = __half22float2(base[(size_t)s3 * 32 + lane]);
                    a0.x += v0.x; a0.y += v0.y;
                    a1.x += v1.x; a1.y += v1.y;
                    a2.x += v2.x; a2.y += v2.y;
                    a3.x += v3.x; a3.y += v3.y;
                }
            }
            if (j < end) {
                int jl = j + lane;
                int sidx = (jl < end) ? g_esrc[jl] : 0;
                int m = end - j;
                for (int t = 0; t < m; t++) {
                    int sv = __shfl_sync(0xffffffffu, sidx, t);
                    float2 v = __half22float2(base[(size_t)sv * 32 + lane]);
                    a0.x += v.x; a0.y += v.y;
                }
            }
            float inv = g_inv[node];
            a0.x = (a0.x + a1.x + a2.x + a3.x) * inv;
            a0.y = (a0.y + a1.y + a2.y + a3.y) * inv;
        }
        *(float2*)&As[lr * AW + lane * 2] = a0;
    }
    __syncthreads();

    // ---- mma chunk0: agg @ Wl
#pragma unroll
    for (int kk = 0; kk < 8; kk++)
        mma_kstep(As, Bs, warpM * 16, warpN * 32, kk * 8, qrow, qcol, acc);
    __syncthreads();

    // ---- phase B: As = h rows (own rows only — no cross-block hazard), Bs = Wr
#pragma unroll
    for (int it = 0; it < 4; it++) {
        int idx = tid + it * 256;
        int r = idx >> 4, c4 = idx & 15;
        int grow = row0 + r;
        float4 v = make_float4(0.f, 0.f, 0.f, 0.f);
        if (grow < NN) v = *(const float4*)(g_h + (size_t)grow * 64 + c4 * 4);
        *(float4*)&As[r * AW + c4 * 4] = v;
        *(float4*)&Bs[r * BW + c4 * 4] = *(const float4*)(Wr + (size_t)r * 64 + c4 * 4);
    }
    __syncthreads();
#pragma unroll
    for (int kk = 0; kk < 8; kk++)
        mma_kstep(As, Bs, warpM * 16, warpN * 32, kk * 8, qrow, qcol, acc);

    // ---- epilogue: h += relu(acc + bl); old h from smem; write NEW fp16 buffer
    __half* __restrict__ dst16 = g_h16[buf ^ 1];
#pragma unroll
    for (int nt = 0; nt < 4; nt++) {
        int gc = warpN * 32 + nt * 8 + qcol * 2;
        float2 bv = *(const float2*)(bl + gc);
#pragma unroll
        for (int half = 0; half < 2; half++) {
            int lr = warpM * 16 + qrow + half * 8;
            int gr = row0 + lr;
            if (gr < NN) {
                float hx = As[lr * AW + gc];
                float hy = As[lr * AW + gc + 1];
                float2 o;
                o.x = hx + fmaxf(acc[nt][half * 2 + 0] + bv.x, 0.f);
                o.y = hy + fmaxf(acc[nt][half * 2 + 1] + bv.y, 0.f);
                *(float2*)(g_h + (size_t)gr * 64 + gc) = o;
                *(__half2*)(dst16 + (size_t)gr * 64 + gc) = __floats2half2_rn(o.x, o.y);
            }
        }
    }
}

// ---------------------------------------------------------------- output GEMM: out = h @ Wout + b_out
__global__ __launch_bounds__(256) void gemm_out_mma(const float* __restrict__ Wout,
                                                    const float* __restrict__ bout,
                                                    float* __restrict__ out) {
    __shared__ __align__(16) float As[64 * AW];
    __shared__ __align__(16) float Bs[64 * BW];
    int tid = threadIdx.x;
    int wid = tid >> 5, lane = tid & 31;
    int warpM = wid & 3, warpN = wid >> 2;
    int qrow = lane >> 2, qcol = lane & 3;
    int row0 = blockIdx.x * 64;
    int col0 = blockIdx.y * 64;
    float acc[4][4];
#pragma unroll
    for (int nt = 0; nt < 4; nt++)
#pragma unroll
        for (int i = 0; i < 4; i++) acc[nt][i] = 0.f;

#pragma unroll
    for (int it = 0; it < 4; it++) {
        int idx = tid + it * 256;
        int r = idx >> 4, c4 = idx & 15;
        int grow = row0 + r;
        float4 v = make_float4(0.f, 0.f, 0.f, 0.f);
        if (grow < NN) v = *(const float4*)(g_h + (size_t)grow * 64 + c4 * 4);
        *(float4*)&As[r * AW + c4 * 4] = v;
        *(float4*)&Bs[r * BW + c4 * 4] = *(const float4*)(Wout + (size_t)r * 256 + col0 + c4 * 4);
    }
    __syncthreads();
#pragma unroll
    for (int kk = 0; kk < 8; kk++)
        mma_kstep(As, Bs, warpM * 16, warpN * 32, kk * 8, qrow, qcol, acc);

#pragma unroll
    for (int nt = 0; nt < 4; nt++) {
        int gc = warpN * 32 + nt * 8 + qcol * 2;
        float2 bv = *(const float2*)(bout + col0 + gc);
#pragma unroll
        for (int half = 0; half < 2; half++) {
            int gr = row0 + warpM * 16 + qrow + half * 8;
            if (gr < NN) {
                float2 o;
                o.x = acc[nt][half * 2 + 0] + bv.x;
                o.y = acc[nt][half * 2 + 1] + bv.y;
                *(float2*)(out + (size_t)gr * 256 + col0 + gc) = o;
            }
        }
    }
}

// ---------------------------------------------------------------- launch
extern "C" void kernel_launch(void* const* d_in, const int* in_sizes, int n_in,
                              void* d_out, int out_size) {
    const float* x    = (const float*)d_in[0];
    const void*  ei   = d_in[1];
    const float* Win  = (const float*)d_in[2];
    const float* bin  = (const float*)d_in[3];
    const float* Wl   = (const float*)d_in[4];
    const float* bl   = (const float*)d_in[5];
    const float* Wr   = (const float*)d_in[6];
    const float* Wout = (const float*)d_in[7];
    const float* bout = (const float*)d_in[8];
    float* out = (float*)d_out;
    int E = in_sizes[1] / 2;

    detect_kernel<<<1, 32>>>((const int*)ei);
    zero_kernel<<<(NN + 255) / 256, 256>>>();
    degree_kernel<<<(E + 255) / 256, 256>>>(ei, E);
    scan_partial_kernel<<<NBLK, 1024>>>();
    scan_bsum_kernel<<<1, 128>>>();
    scan_add_kernel<<<NBLK, 1024>>>();
    scatter_kernel<<<(E + 255) / 256, 256>>>(ei, E);

    gemm_in_mma<<<MBLK, 256>>>(x, Win, bin);

    for (int i = 0; i < 4; i++)
        layer_fused_kernel<<<MBLK, 256>>>(Wl + i * HD * HD, Wr + i * HD * HD,
                                          bl + i * HD, i & 1);

    gemm_out_mma<<<dim3(MBLK, 4), 256>>>(Wout, bout, out);
}

// round 9
// speedup vs baseline: 1.2173x; 1.2173x over previous
#include <cuda_runtime.h>
#include <cuda_fp16.h>
#include <cstdint>

#define NN   100000
#define HD   64
#define EMAX 3200000
#define NBLK ((NN + 1023) / 1024)   // 98
#define MBLK ((NN + 63) / 64)       // 1563

// ---- scratch (device globals; no allocation allowed) ----
__device__ __align__(16) float  g_h[NN * HD];     // node features fp32 (25.6 MB)
__device__ __align__(16) __half g_h16[NN * HD];   // fp16 mirror for gather (12.8 MB)
__device__ __align__(16) float  g_agg[NN * HD];   // aggregated neighbor features
__device__ int   g_cnt[NN];
__device__ float g_inv[NN];
__device__ int   g_rowptr[NN + 1];
__device__ int   g_fill[NN];
__device__ int   g_esrc[EMAX];
__device__ int   g_is64;
__device__ int   g_bsum[NBLK];
__device__ int   g_boff[NBLK];

// ---------------------------------------------------------------- fp16 split mma helpers
__device__ __forceinline__ void mma_f16(float* d, const uint32_t* a, const uint32_t* b) {
    asm volatile(
        "mma.sync.aligned.m16n8k16.row.col.f32.f16.f16.f32 "
        "{%0,%1,%2,%3}, {%4,%5,%6,%7}, {%8,%9}, {%0,%1,%2,%3};\n"
        : "+f"(d[0]), "+f"(d[1]), "+f"(d[2]), "+f"(d[3])
        : "r"(a[0]), "r"(a[1]), "r"(a[2]), "r"(a[3]), "r"(b[0]), "r"(b[1]));
}
// split a float into hi fp16 + lo fp16 residual
__device__ __forceinline__ void split2(float a, float b, __half2& hi, __half2& lo) {
    __half ha = __float2half_rn(a), hb = __float2half_rn(b);
    hi = __halves2half2(ha, hb);
    lo = __floats2half2_rn(a - __half2float(ha), b - __half2float(hb));
}

// ---------------------------------------------------------------- dtype probe
__global__ void detect_kernel(const int* __restrict__ ei32) {
    if (threadIdx.x == 0 && blockIdx.x == 0) {
        int nz = 0;
        for (int k = 0; k < 64; k++) nz |= ei32[2 * k + 1];
        g_is64 = (nz == 0) ? 1 : 0;
    }
}
__device__ __forceinline__ int load_idx(const void* ei, size_t pos) {
    if (g_is64) return (int)((const long long*)ei)[pos];
    return ((const int*)ei)[pos];
}

// ---------------------------------------------------------------- zero / degree
__global__ void zero_kernel() {
    int i = blockIdx.x * blockDim.x + threadIdx.x;
    if (i < NN) { g_cnt[i] = 0; g_fill[i] = 0; }
}
__global__ void degree_kernel(const void* __restrict__ ei, int E) {
    int e = blockIdx.x * blockDim.x + threadIdx.x;
    if (e < E) {
        int d = load_idx(ei, (size_t)E + e);
        if ((unsigned)d < NN) atomicAdd(&g_cnt[d], 1);
    }
}

// ---------------------------------------------------------------- hierarchical scan
__global__ __launch_bounds__(1024) void scan_partial_kernel() {
    __shared__ int s[1024];
    int tid = threadIdx.x, b = blockIdx.x;
    int i = b * 1024 + tid;
    int v = (i < NN) ? g_cnt[i] : 0;
    if (i < NN) g_inv[i] = 1.0f / fmaxf((float)v, 1.0f);
    s[tid] = v;
    __syncthreads();
#pragma unroll
    for (int off = 1; off < 1024; off <<= 1) {
        int t = (tid >= off) ? s[tid - off] : 0;
        __syncthreads();
        s[tid] += t;
        __syncthreads();
    }
    if (i < NN) g_rowptr[i + 1] = s[tid];
    if (tid == 1023) g_bsum[b] = s[1023];
    if (i == 0) g_rowptr[0] = 0;
}
__global__ void scan_bsum_kernel() {
    __shared__ int s[128];
    int tid = threadIdx.x;
    int v = (tid < NBLK) ? g_bsum[tid] : 0;
    s[tid] = v;
    __syncthreads();
#pragma unroll
    for (int off = 1; off < 128; off <<= 1) {
        int t = (tid >= off) ? s[tid - off] : 0;
        __syncthreads();
        s[tid] += t;
        __syncthreads();
    }
    if (tid < NBLK) g_boff[tid] = s[tid] - v;
}
__global__ __launch_bounds__(1024) void scan_add_kernel() {
    int i = blockIdx.x * 1024 + threadIdx.x;
    if (i < NN) g_rowptr[i + 1] += g_boff[blockIdx.x];
}

// ---------------------------------------------------------------- counting-sort scatter
__global__ void scatter_kernel(const void* __restrict__ ei, int E) {
    int e = blockIdx.x * blockDim.x + threadIdx.x;
    if (e < E) {
        int srcv = load_idx(ei, (size_t)e);
        int d    = load_idx(ei, (size_t)E + e);
        if ((unsigned)d < NN && (unsigned)srcv < NN) {
            int pos = g_rowptr[d] + atomicAdd(&g_fill[d], 1);
            if ((unsigned)pos < EMAX) g_esrc[pos] = srcv;
        }
    }
}

// ---------------------------------------------------------------- aggregate (warp per node, fp16 gather, 8-deep ILP)
__global__ __launch_bounds__(256) void aggregate_kernel() {
    int gtid = blockIdx.x * blockDim.x + threadIdx.x;
    int w = gtid >> 5, lane = gtid & 31;
    if (w >= NN) return;
    int beg = g_rowptr[w], end = g_rowptr[w + 1];
    const __half2* __restrict__ base = (const __half2*)g_h16;

    float2 ac[8];
#pragma unroll
    for (int i = 0; i < 8; i++) ac[i] = make_float2(0.f, 0.f);
    int n = end - beg;
    int nfull = n & ~31;
    int j = beg;
    for (; j < beg + nfull; j += 32) {
        int sidx = g_esrc[j + lane];
#pragma unroll
        for (int t = 0; t < 32; t += 8) {
            int sv[8];
#pragma unroll
            for (int u = 0; u < 8; u++) sv[u] = __shfl_sync(0xffffffffu, sidx, t + u);
            float2 v[8];
#pragma unroll
            for (int u = 0; u < 8; u++) v[u] = __half22float2(base[(size_t)sv[u] * 32 + lane]);
#pragma unroll
            for (int u = 0; u < 8; u++) { ac[u].x += v[u].x; ac[u].y += v[u].y; }
        }
    }
    if (j < end) {
        int jl = j + lane;
        int sidx = (jl < end) ? g_esrc[jl] : 0;
        int m = end - j;
        for (int t = 0; t < m; t++) {
            int sv = __shfl_sync(0xffffffffu, sidx, t);
            float2 v = __half22float2(base[(size_t)sv * 32 + lane]);
            ac[0].x += v.x; ac[0].y += v.y;
        }
    }
    float inv = g_inv[w];
    float2 acc = make_float2(0.f, 0.f);
#pragma unroll
    for (int i = 0; i < 8; i++) { acc.x += ac[i].x; acc.y += ac[i].y; }
    acc.x *= inv; acc.y *= inv;
    *(float2*)(g_agg + (size_t)w * HD + lane * 2) = acc;
}

// ================================================================ fp16-split MMA GEMMs
// A planes: [64 rows][32 half2] stride A2W=36 (bank 4*qrow+qcol bijective)
// B planes: [32 k2  ][64 n    ] stride B2W=72 (bank 8*qcol+qrow bijective)
#define A2W 36
#define B2W 72

// per-thread A-tile stage: 4x float4 (16 floats of one 64-row x 64-k chunk)
__device__ __forceinline__ void storeA_planes(__half2* Ah, __half2* Al,
                                              const float4* va, int tid) {
#pragma unroll
    for (int it = 0; it < 4; it++) {
        int idx = tid + it * 256;
        int r = idx >> 4, c4 = idx & 15;
        __half2 h0, l0, h1, l1;
        split2(va[it].x, va[it].y, h0, l0);
        split2(va[it].z, va[it].w, h1, l1);
        __half2* ph = Ah + r * A2W + c4 * 2;
        __half2* pl = Al + r * A2W + c4 * 2;
        *(uint2*)ph = make_uint2(*(uint32_t*)&h0, *(uint32_t*)&h1);
        *(uint2*)pl = make_uint2(*(uint32_t*)&l0, *(uint32_t*)&l1);
    }
}
// per-thread B-tile stage: rows 2k2,2k2+1 x 8 n values -> 8 half2 per plane (two uint4)
__device__ __forceinline__ void storeB_planes(__half2* Bh, __half2* Bl,
                                              const float4* vb, int tid) {
    int k2 = tid >> 3, ng = (tid & 7) * 8;
    const float* r0 = (const float*)&vb[0];  // vb[0],vb[1] = row 2k2   (8 floats)
    const float* r1 = (const float*)&vb[2];  // vb[2],vb[3] = row 2k2+1 (8 floats)
    __half2 hh[8], ll[8];
#pragma unroll
    for (int jj = 0; jj < 8; jj++) split2(r0[jj], r1[jj], hh[jj], ll[jj]);
    uint4* ph = (uint4*)(Bh + k2 * B2W + ng);
    uint4* pl = (uint4*)(Bl + k2 * B2W + ng);
    ph[0] = make_uint4(*(uint32_t*)&hh[0], *(uint32_t*)&hh[1], *(uint32_t*)&hh[2], *(uint32_t*)&hh[3]);
    ph[1] = make_uint4(*(uint32_t*)&hh[4], *(uint32_t*)&hh[5], *(uint32_t*)&hh[6], *(uint32_t*)&hh[7]);
    pl[0] = make_uint4(*(uint32_t*)&ll[0], *(uint32_t*)&ll[1], *(uint32_t*)&ll[2], *(uint32_t*)&ll[3]);
    pl[1] = make_uint4(*(uint32_t*)&ll[4], *(uint32_t*)&ll[5], *(uint32_t*)&ll[6], *(uint32_t*)&ll[7]);
}

// one k16 step: 3 split-product mmas per 8-col tile
__device__ __forceinline__ void mma_kstep16(const __half2* Ah, const __half2* Al,
                                            const __half2* Bh, const __half2* Bl,
                                            int m0, int n0, int k2b,
                                            int qrow, int qcol, float acc[4][4]) {
    uint32_t ah[4], al[4];
    int ra = (m0 + qrow) * A2W + k2b + qcol;
    ah[0] = *(const uint32_t*)&Ah[ra];
    ah[1] = *(const uint32_t*)&Ah[ra + 8 * A2W];
    ah[2] = *(const uint32_t*)&Ah[ra + 4];
    ah[3] = *(const uint32_t*)&Ah[ra + 8 * A2W + 4];
    al[0] = *(const uint32_t*)&Al[ra];
    al[1] = *(const uint32_t*)&Al[ra + 8 * A2W];
    al[2] = *(const uint32_t*)&Al[ra + 4];
    al[3] = *(const uint32_t*)&Al[ra + 8 * A2W + 4];
#pragma unroll
    for (int nt = 0; nt < 4; nt++) {
        int nn = n0 + nt * 8;
        int rb = (k2b + qcol) * B2W + nn + qrow;
        uint32_t bh[2], bl2[2];
        bh[0]  = *(const uint32_t*)&Bh[rb];
        bh[1]  = *(const uint32_t*)&Bh[rb + 4 * B2W];
        bl2[0] = *(const uint32_t*)&Bl[rb];
        bl2[1] = *(const uint32_t*)&Bl[rb + 4 * B2W];
        mma_f16(acc[nt], ah, bh);
        mma_f16(acc[nt], al, bh);
        mma_f16(acc[nt], ah, bl2);
    }
}

// ---------------------------------------------------------------- input GEMM: h = x @ Win + b_in
// 8 K-chunks of 64; register-staged prefetch overlaps HBM reads with mma.
__global__ __launch_bounds__(256) void gemm_in_mma(const float* __restrict__ x,
                                                   const float* __restrict__ Win,
                                                   const float* __restrict__ bin) {
    __shared__ __align__(16) __half2 Ah[64 * A2W], Al[64 * A2W];
    __shared__ __align__(16) __half2 Bh[32 * B2W], Bl[32 * B2W];
    int tid = threadIdx.x;
    int wid = tid >> 5, lane = tid & 31;
    int warpM = wid & 3, warpN = wid >> 2;
    int qrow = lane >> 2, qcol = lane & 3;
    int row0 = blockIdx.x * 64;
    float acc[4][4];
#pragma unroll
    for (int nt = 0; nt < 4; nt++)
#pragma unroll
        for (int i = 0; i < 4; i++) acc[nt][i] = 0.f;

    float4 va[4], vb[4];
    // prologue: load chunk 0
    {
        int k2 = tid >> 3, ng = (tid & 7) * 8;
#pragma unroll
        for (int it = 0; it < 4; it++) {
            int idx = tid + it * 256;
            int r = idx >> 4, c4 = idx & 15;
            int grow = row0 + r;
            va[it] = (grow < NN) ? *(const float4*)(x + (size_t)grow * 512 + c4 * 4)
                                 : make_float4(0.f, 0.f, 0.f, 0.f);
        }
        vb[0] = *(const float4*)(Win + (size_t)(2 * k2) * 64 + ng);
        vb[1] = *(const float4*)(Win + (size_t)(2 * k2) * 64 + ng + 4);
        vb[2] = *(const float4*)(Win + (size_t)(2 * k2 + 1) * 64 + ng);
        vb[3] = *(const float4*)(Win + (size_t)(2 * k2 + 1) * 64 + ng + 4);
    }
#pragma unroll 1
    for (int c = 0; c < 8; c++) {
        storeA_planes(Ah, Al, va, tid);
        storeB_planes(Bh, Bl, vb, tid);
        __syncthreads();
        if (c < 7) {
            int kc = (c + 1) * 64;
            int k2 = tid >> 3, ng = (tid & 7) * 8;
#pragma unroll
            for (int it = 0; it < 4; it++) {
                int idx = tid + it * 256;
                int r = idx >> 4, c4 = idx & 15;
                int grow = row0 + r;
                va[it] = (grow < NN) ? *(const float4*)(x + (size_t)grow * 512 + kc + c4 * 4)
                                     : make_float4(0.f, 0.f, 0.f, 0.f);
            }
            vb[0] = *(const float4*)(Win + (size_t)(kc + 2 * k2) * 64 + ng);
            vb[1] = *(const float4*)(Win + (size_t)(kc + 2 * k2) * 64 + ng + 4);
            vb[2] = *(const float4*)(Win + (size_t)(kc + 2 * k2 + 1) * 64 + ng);
            vb[3] = *(const float4*)(Win + (size_t)(kc + 2 * k2 + 1) * 64 + ng + 4);
        }
#pragma unroll
        for (int kk = 0; kk < 4; kk++)
            mma_kstep16(Ah, Al, Bh, Bl, warpM * 16, warpN * 32, kk * 8, qrow, qcol, acc);
        __syncthreads();
    }
#pragma unroll
    for (int nt = 0; nt < 4; nt++) {
        int gc = warpN * 32 + nt * 8 + qcol * 2;
        float2 bv = *(const float2*)(bin + gc);
#pragma unroll
        for (int half = 0; half < 2; half++) {
            int gr = row0 + warpM * 16 + qrow + half * 8;
            if (gr < NN) {
                float2 o;
                o.x = acc[nt][half * 2 + 0] + bv.x;
                o.y = acc[nt][half * 2 + 1] + bv.y;
                *(float2*)(g_h + (size_t)gr * 64 + gc) = o;
                *(__half2*)(g_h16 + (size_t)gr * 64 + gc) = __floats2half2_rn(o.x, o.y);
            }
        }
    }
}

// ---------------------------------------------------------------- layer GEMM:
// h = h + relu(agg @ Wl + bl + h @ Wr)   (2 K-chunks: agg/Wl then h/Wr)
__global__ __launch_bounds__(256) void gemm_layer_mma(const float* __restrict__ Wl,
                                                      const float* __restrict__ Wr,
                                                      const float* __restrict__ bl) {
    __shared__ __align__(16) __half2 Ah[64 * A2W], Al[64 * A2W];
    __shared__ __align__(16) __half2 Bh[32 * B2W], Bl[32 * B2W];
    int tid = threadIdx.x;
    int wid = tid >> 5, lane = tid & 31;
    int warpM = wid & 3, warpN = wid >> 2;
    int qrow = lane >> 2, qcol = lane & 3;
    int row0 = blockIdx.x * 64;
    float acc[4][4];
#pragma unroll
    for (int nt = 0; nt < 4; nt++)
#pragma unroll
        for (int i = 0; i < 4; i++) acc[nt][i] = 0.f;

#pragma unroll
    for (int c = 0; c < 2; c++) {
        const float* Asrc = c ? g_h : g_agg;
        const float* Bsrc = c ? Wr : Wl;
        float4 va[4], vb[4];
        int k2 = tid >> 3, ng = (tid & 7) * 8;
#pragma unroll
        for (int it = 0; it < 4; it++) {
            int idx = tid + it * 256;
            int r = idx >> 4, c4 = idx & 15;
            int grow = row0 + r;
            va[it] = (grow < NN) ? *(const float4*)(Asrc + (size_t)grow * 64 + c4 * 4)
                                 : make_float4(0.f, 0.f, 0.f, 0.f);
        }
        vb[0] = *(const float4*)(Bsrc + (size_t)(2 * k2) * 64 + ng);
        vb[1] = *(const float4*)(Bsrc + (size_t)(2 * k2) * 64 + ng + 4);
        vb[2] = *(const float4*)(Bsrc + (size_t)(2 * k2 + 1) * 64 + ng);
        vb[3] = *(const float4*)(Bsrc + (size_t)(2 * k2 + 1) * 64 + ng + 4);
        storeA_planes(Ah, Al, va, tid);
        storeB_planes(Bh, Bl, vb, tid);
        __syncthreads();
#pragma unroll
        for (int kk = 0; kk < 4; kk++)
            mma_kstep16(Ah, Al, Bh, Bl, warpM * 16, warpN * 32, kk * 8, qrow, qcol, acc);
        __syncthreads();
    }
#pragma unroll
    for (int nt = 0; nt < 4; nt++) {
        int gc = warpN * 32 + nt * 8 + qcol * 2;
        float2 bv = *(const float2*)(bl + gc);
#pragma unroll
        for (int half = 0; half < 2; half++) {
            int gr = row0 + warpM * 16 + qrow + half * 8;
            if (gr < NN) {
                float2 old = *(const float2*)(g_h + (size_t)gr * 64 + gc);
                float2 o;
                o.x = old.x + fmaxf(acc[nt][half * 2 + 0] + bv.x, 0.f);
                o.y = old.y + fmaxf(acc[nt][half * 2 + 1] + bv.y, 0.f);
                *(float2*)(g_h + (size_t)gr * 64 + gc) = o;
                *(__half2*)(g_h16 + (size_t)gr * 64 + gc) = __floats2half2_rn(o.x, o.y);
            }
        }
    }
}

// ---------------------------------------------------------------- output GEMM: out = h @ Wout + b_out
__global__ __launch_bounds__(256) void gemm_out_mma(const float* __restrict__ Wout,
                                                    const float* __restrict__ bout,
                                                    float* __restrict__ out) {
    __shared__ __align__(16) __half2 Ah[64 * A2W], Al[64 * A2W];
    __shared__ __align__(16) __half2 Bh[32 * B2W], Bl[32 * B2W];
    int tid = threadIdx.x;
    int wid = tid >> 5, lane = tid & 31;
    int warpM = wid & 3, warpN = wid >> 2;
    int qrow = lane >> 2, qcol = lane & 3;
    int row0 = blockIdx.x * 64;
    int col0 = blockIdx.y * 64;
    float acc[4][4];
#pragma unroll
    for (int nt = 0; nt < 4; nt++)
#pragma unroll
        for (int i = 0; i < 4; i++) acc[nt][i] = 0.f;

    {
        float4 va[4], vb[4];
        int k2 = tid >> 3, ng = (tid & 7) * 8;
#pragma unroll
        for (int it = 0; it < 4; it++) {
            int idx = tid + it * 256;
            int r = idx >> 4, c4 = idx & 15;
            int grow = row0 + r;
            va[it] = (grow < NN) ? *(const float4*)(g_h + (size_t)grow * 64 + c4 * 4)
                                 : make_float4(0.f, 0.f, 0.f, 0.f);
        }
        vb[0] = *(const float4*)(Wout + (size_t)(2 * k2) * 256 + col0 + ng);
        vb[1] = *(const float4*)(Wout + (size_t)(2 * k2) * 256 + col0 + ng + 4);
        vb[2] = *(const float4*)(Wout + (size_t)(2 * k2 + 1) * 256 + col0 + ng);
        vb[3] = *(const float4*)(Wout + (size_t)(2 * k2 + 1) * 256 + col0 + ng + 4);
        storeA_planes(Ah, Al, va, tid);
        storeB_planes(Bh, Bl, vb, tid);
    }
    __syncthreads();
#pragma unroll
    for (int kk = 0; kk < 4; kk++)
        mma_kstep16(Ah, Al, Bh, Bl, warpM * 16, warpN * 32, kk * 8, qrow, qcol, acc);

#pragma unroll
    for (int nt = 0; nt < 4; nt++) {
        int gc = warpN * 32 + nt * 8 + qcol * 2;
        float2 bv = *(const float2*)(bout + col0 + gc);
#pragma unroll
        for (int half = 0; half < 2; half++) {
            int gr = row0 + warpM * 16 + qrow + half * 8;
            if (gr < NN) {
                float2 o;
                o.x = acc[nt][half * 2 + 0] + bv.x;
                o.y = acc[nt][half * 2 + 1] + bv.y;
                *(float2*)(out + (size_t)gr * 256 + col0 + gc) = o;
            }
        }
    }
}

// ---------------------------------------------------------------- launch
extern "C" void kernel_launch(void* const* d_in, const int* in_sizes, int n_in,
                              void* d_out, int out_size) {
    const float* x    = (const float*)d_in[0];
    const void*  ei   = d_in[1];
    const float* Win  = (const float*)d_in[2];
    const float* bin  = (const float*)d_in[3];
    const float* Wl   = (const float*)d_in[4];
    const float* bl   = (const float*)d_in[5];
    const float* Wr   = (const float*)d_in[6];
    const float* Wout = (const float*)d_in[7];
    const float* bout = (const float*)d_in[8];
    float* out = (float*)d_out;
    int E = in_sizes[1] / 2;

    detect_kernel<<<1, 32>>>((const int*)ei);
    zero_kernel<<<(NN + 255) / 256, 256>>>();
    degree_kernel<<<(E + 255) / 256, 256>>>(ei, E);
    scan_partial_kernel<<<NBLK, 1024>>>();
    scan_bsum_kernel<<<1, 128>>>();
    scan_add_kernel<<<NBLK, 1024>>>();
    scatter_kernel<<<(E + 255) / 256, 256>>>(ei, E);

    gemm_in_mma<<<MBLK, 256>>>(x, Win, bin);

    for (int i = 0; i < 4; i++) {
        aggregate_kernel<<<(NN * 32 + 255) / 256, 256>>>();
        gemm_layer_mma<<<MBLK, 256>>>(Wl + i * HD * HD, Wr + i * HD * HD, bl + i * HD);
    }

    gemm_out_mma<<<dim3(MBLK, 4), 256>>>(Wout, bout, out);
}

// round 10
// speedup vs baseline: 1.2504x; 1.0272x over previous
#include <cuda_runtime.h>
#include <cuda_fp16.h>
#include <cstdint>

#define NN   100000
#define HD   64
#define EMAX 3200000
#define NBLK ((NN + 1023) / 1024)   // 98
#define MBLK ((NN + 63) / 64)       // 1563

// ---- scratch (device globals; no allocation allowed) ----
__device__ __align__(16) float  g_h[NN * HD];     // node features fp32 (25.6 MB)
__device__ __align__(16) __half g_h16[NN * HD];   // fp16 mirror for gather (12.8 MB)
__device__ __align__(16) float  g_agg[NN * HD];   // aggregated neighbor features
__device__ int   g_cnt[NN];
__device__ float g_inv[NN];
__device__ int   g_rowptr[NN + 1];
__device__ int   g_fill[NN];
__device__ int   g_esrc[EMAX];
__device__ int   g_is64;
__device__ int   g_bsum[NBLK];
__device__ int   g_boff[NBLK];

// ---------------------------------------------------------------- fp16 split mma helpers
__device__ __forceinline__ void mma_f16(float* d, const uint32_t* a, const uint32_t* b) {
    asm volatile(
        "mma.sync.aligned.m16n8k16.row.col.f32.f16.f16.f32 "
        "{%0,%1,%2,%3}, {%4,%5,%6,%7}, {%8,%9}, {%0,%1,%2,%3};\n"
        : "+f"(d[0]), "+f"(d[1]), "+f"(d[2]), "+f"(d[3])
        : "r"(a[0]), "r"(a[1]), "r"(a[2]), "r"(a[3]), "r"(b[0]), "r"(b[1]));
}
__device__ __forceinline__ void split2(float a, float b, __half2& hi, __half2& lo) {
    __half ha = __float2half_rn(a), hb = __float2half_rn(b);
    hi = __halves2half2(ha, hb);
    lo = __floats2half2_rn(a - __half2float(ha), b - __half2float(hb));
}

// ---------------------------------------------------------------- dtype probe
__global__ void detect_kernel(const int* __restrict__ ei32) {
    if (threadIdx.x == 0 && blockIdx.x == 0) {
        int nz = 0;
        for (int k = 0; k < 64; k++) nz |= ei32[2 * k + 1];
        g_is64 = (nz == 0) ? 1 : 0;
    }
}
__device__ __forceinline__ int load_idx(const void* ei, size_t pos) {
    if (g_is64) return (int)((const long long*)ei)[pos];
    return ((const int*)ei)[pos];
}

// ---------------------------------------------------------------- zero / degree
__global__ void zero_kernel() {
    int i = blockIdx.x * blockDim.x + threadIdx.x;
    if (i < NN) { g_cnt[i] = 0; g_fill[i] = 0; }
}
__global__ void degree_kernel(const void* __restrict__ ei, int E) {
    int e = blockIdx.x * blockDim.x + threadIdx.x;
    if (e < E) {
        int d = load_idx(ei, (size_t)E + e);
        if ((unsigned)d < NN) atomicAdd(&g_cnt[d], 1);
    }
}

// ---------------------------------------------------------------- hierarchical scan
__global__ __launch_bounds__(1024) void scan_partial_kernel() {
    __shared__ int s[1024];
    int tid = threadIdx.x, b = blockIdx.x;
    int i = b * 1024 + tid;
    int v = (i < NN) ? g_cnt[i] : 0;
    if (i < NN) g_inv[i] = 1.0f / fmaxf((float)v, 1.0f);
    s[tid] = v;
    __syncthreads();
#pragma unroll
    for (int off = 1; off < 1024; off <<= 1) {
        int t = (tid >= off) ? s[tid - off] : 0;
        __syncthreads();
        s[tid] += t;
        __syncthreads();
    }
    if (i < NN) g_rowptr[i + 1] = s[tid];
    if (tid == 1023) g_bsum[b] = s[1023];
    if (i == 0) g_rowptr[0] = 0;
}
__global__ void scan_bsum_kernel() {
    __shared__ int s[128];
    int tid = threadIdx.x;
    int v = (tid < NBLK) ? g_bsum[tid] : 0;
    s[tid] = v;
    __syncthreads();
#pragma unroll
    for (int off = 1; off < 128; off <<= 1) {
        int t = (tid >= off) ? s[tid - off] : 0;
        __syncthreads();
        s[tid] += t;
        __syncthreads();
    }
    if (tid < NBLK) g_boff[tid] = s[tid] - v;
}
__global__ __launch_bounds__(1024) void scan_add_kernel() {
    int i = blockIdx.x * 1024 + threadIdx.x;
    if (i < NN) g_rowptr[i + 1] += g_boff[blockIdx.x];
}

// ---------------------------------------------------------------- counting-sort scatter
__global__ void scatter_kernel(const void* __restrict__ ei, int E) {
    int e = blockIdx.x * blockDim.x + threadIdx.x;
    if (e < E) {
        int srcv = load_idx(ei, (size_t)e);
        int d    = load_idx(ei, (size_t)E + e);
        if ((unsigned)d < NN && (unsigned)srcv < NN) {
            int pos = g_rowptr[d] + atomicAdd(&g_fill[d], 1);
            if ((unsigned)pos < EMAX) g_esrc[pos] = srcv;
        }
    }
}

// ---------------------------------------------------------------- aggregate (warp per node, fp16 gather, 8-deep ILP)
__global__ __launch_bounds__(256) void aggregate_kernel() {
    int gtid = blockIdx.x * blockDim.x + threadIdx.x;
    int w = gtid >> 5, lane = gtid & 31;
    if (w >= NN) return;
    int beg = g_rowptr[w], end = g_rowptr[w + 1];
    const __half2* __restrict__ base = (const __half2*)g_h16;

    float2 ac[8];
#pragma unroll
    for (int i = 0; i < 8; i++) ac[i] = make_float2(0.f, 0.f);
    int n = end - beg;
    int nfull = n & ~31;
    int j = beg;
    for (; j < beg + nfull; j += 32) {
        int sidx = g_esrc[j + lane];
#pragma unroll
        for (int t = 0; t < 32; t += 8) {
            int sv[8];
#pragma unroll
            for (int u = 0; u < 8; u++) sv[u] = __shfl_sync(0xffffffffu, sidx, t + u);
            float2 v[8];
#pragma unroll
            for (int u = 0; u < 8; u++) v[u] = __half22float2(base[(size_t)sv[u] * 32 + lane]);
#pragma unroll
            for (int u = 0; u < 8; u++) { ac[u].x += v[u].x; ac[u].y += v[u].y; }
        }
    }
    if (j < end) {
        int jl = j + lane;
        int sidx = (jl < end) ? g_esrc[jl] : 0;
        int m = end - j;
        for (int t = 0; t < m; t++) {
            int sv = __shfl_sync(0xffffffffu, sidx, t);
            float2 v = __half22float2(base[(size_t)sv * 32 + lane]);
            ac[0].x += v.x; ac[0].y += v.y;
        }
    }
    float inv = g_inv[w];
    float2 acc = make_float2(0.f, 0.f);
#pragma unroll
    for (int i = 0; i < 8; i++) { acc.x += ac[i].x; acc.y += ac[i].y; }
    acc.x *= inv; acc.y *= inv;
    *(float2*)(g_agg + (size_t)w * HD + lane * 2) = acc;
}

// ================================================================ fp16-split MMA GEMMs
#define A2W 36
#define B2W 72

__device__ __forceinline__ void storeA_planes(__half2* Ah, __half2* Al,
                                              const float4* va, int tid) {
#pragma unroll
    for (int it = 0; it < 4; it++) {
        int idx = tid + it * 256;
        int r = idx >> 4, c4 = idx & 15;
        __half2 h0, l0, h1, l1;
        split2(va[it].x, va[it].y, h0, l0);
        split2(va[it].z, va[it].w, h1, l1);
        __half2* ph = Ah + r * A2W + c4 * 2;
        __half2* pl = Al + r * A2W + c4 * 2;
        *(uint2*)ph = make_uint2(*(uint32_t*)&h0, *(uint32_t*)&h1);
        *(uint2*)pl = make_uint2(*(uint32_t*)&l0, *(uint32_t*)&l1);
    }
}
__device__ __forceinline__ void storeB_planes(__half2* Bh, __half2* Bl,
                                              const float4* vb, int tid) {
    int k2 = tid >> 3, ng = (tid & 7) * 8;
    const float* r0 = (const float*)&vb[0];
    const float* r1 = (const float*)&vb[2];
    __half2 hh[8], ll[8];
#pragma unroll
    for (int jj = 0; jj < 8; jj++) split2(r0[jj], r1[jj], hh[jj], ll[jj]);
    uint4* ph = (uint4*)(Bh + k2 * B2W + ng);
    uint4* pl = (uint4*)(Bl + k2 * B2W + ng);
    ph[0] = make_uint4(*(uint32_t*)&hh[0], *(uint32_t*)&hh[1], *(uint32_t*)&hh[2], *(uint32_t*)&hh[3]);
    ph[1] = make_uint4(*(uint32_t*)&hh[4], *(uint32_t*)&hh[5], *(uint32_t*)&hh[6], *(uint32_t*)&hh[7]);
    pl[0] = make_uint4(*(uint32_t*)&ll[0], *(uint32_t*)&ll[1], *(uint32_t*)&ll[2], *(uint32_t*)&ll[3]);
    pl[1] = make_uint4(*(uint32_t*)&ll[4], *(uint32_t*)&ll[5], *(uint32_t*)&ll[6], *(uint32_t*)&ll[7]);
}

__device__ __forceinline__ void mma_kstep16(const __half2* Ah, const __half2* Al,
                                            const __half2* Bh, const __half2* Bl,
                                            int m0, int n0, int k2b,
                                            int qrow, int qcol, float acc[4][4]) {
    uint32_t ah[4], al[4];
    int ra = (m0 + qrow) * A2W + k2b + qcol;
    ah[0] = *(const uint32_t*)&Ah[ra];
    ah[1] = *(const uint32_t*)&Ah[ra + 8 * A2W];
    ah[2] = *(const uint32_t*)&Ah[ra + 4];
    ah[3] = *(const uint32_t*)&Ah[ra + 8 * A2W + 4];
    al[0] = *(const uint32_t*)&Al[ra];
    al[1] = *(const uint32_t*)&Al[ra + 8 * A2W];
    al[2] = *(const uint32_t*)&Al[ra + 4];
    al[3] = *(const uint32_t*)&Al[ra + 8 * A2W + 4];
#pragma unroll
    for (int nt = 0; nt < 4; nt++) {
        int nn = n0 + nt * 8;
        int rb = (k2b + qcol) * B2W + nn + qrow;
        uint32_t bh[2], bl2[2];
        bh[0]  = *(const uint32_t*)&Bh[rb];
        bh[1]  = *(const uint32_t*)&Bh[rb + 4 * B2W];
        bl2[0] = *(const uint32_t*)&Bl[rb];
        bl2[1] = *(const uint32_t*)&Bl[rb + 4 * B2W];
        mma_f16(acc[nt], ah, bh);
        mma_f16(acc[nt], al, bh);
        mma_f16(acc[nt], ah, bl2);
    }
}

// ---------------------------------------------------------------- input GEMM: h = x @ Win + b_in
__global__ __launch_bounds__(256) void gemm_in_mma(const float* __restrict__ x,
                                                   const float* __restrict__ Win,
                                                   const float* __restrict__ bin) {
    __shared__ __align__(16) __half2 Ah[64 * A2W], Al[64 * A2W];
    __shared__ __align__(16) __half2 Bh[32 * B2W], Bl[32 * B2W];
    int tid = threadIdx.x;
    int wid = tid >> 5, lane = tid & 31;
    int warpM = wid & 3, warpN = wid >> 2;
    int qrow = lane >> 2, qcol = lane & 3;
    int row0 = blockIdx.x * 64;
    float acc[4][4];
#pragma unroll
    for (int nt = 0; nt < 4; nt++)
#pragma unroll
        for (int i = 0; i < 4; i++) acc[nt][i] = 0.f;

    float4 va[4], vb[4];
    {
        int k2 = tid >> 3, ng = (tid & 7) * 8;
#pragma unroll
        for (int it = 0; it < 4; it++) {
            int idx = tid + it * 256;
            int r = idx >> 4, c4 = idx & 15;
            int grow = row0 + r;
            va[it] = (grow < NN) ? *(const float4*)(x + (size_t)grow * 512 + c4 * 4)
                                 : make_float4(0.f, 0.f, 0.f, 0.f);
        }
        vb[0] = *(const float4*)(Win + (size_t)(2 * k2) * 64 + ng);
        vb[1] = *(const float4*)(Win + (size_t)(2 * k2) * 64 + ng + 4);
        vb[2] = *(const float4*)(Win + (size_t)(2 * k2 + 1) * 64 + ng);
        vb[3] = *(const float4*)(Win + (size_t)(2 * k2 + 1) * 64 + ng + 4);
    }
#pragma unroll 1
    for (int c = 0; c < 8; c++) {
        storeA_planes(Ah, Al, va, tid);
        storeB_planes(Bh, Bl, vb, tid);
        __syncthreads();
        if (c < 7) {
            int kc = (c + 1) * 64;
            int k2 = tid >> 3, ng = (tid & 7) * 8;
#pragma unroll
            for (int it = 0; it < 4; it++) {
                int idx = tid + it * 256;
                int r = idx >> 4, c4 = idx & 15;
                int grow = row0 + r;
                va[it] = (grow < NN) ? *(const float4*)(x + (size_t)grow * 512 + kc + c4 * 4)
                                     : make_float4(0.f, 0.f, 0.f, 0.f);
            }
            vb[0] = *(const float4*)(Win + (size_t)(kc + 2 * k2) * 64 + ng);
            vb[1] = *(const float4*)(Win + (size_t)(kc + 2 * k2) * 64 + ng + 4);
            vb[2] = *(const float4*)(Win + (size_t)(kc + 2 * k2 + 1) * 64 + ng);
            vb[3] = *(const float4*)(Win + (size_t)(kc + 2 * k2 + 1) * 64 + ng + 4);
        }
#pragma unroll
        for (int kk = 0; kk < 4; kk++)
            mma_kstep16(Ah, Al, Bh, Bl, warpM * 16, warpN * 32, kk * 8, qrow, qcol, acc);
        __syncthreads();
    }
#pragma unroll
    for (int nt = 0; nt < 4; nt++) {
        int gc = warpN * 32 + nt * 8 + qcol * 2;
        float2 bv = *(const float2*)(bin + gc);
#pragma unroll
        for (int half = 0; half < 2; half++) {
            int gr = row0 + warpM * 16 + qrow + half * 8;
            if (gr < NN) {
                float2 o;
                o.x = acc[nt][half * 2 + 0] + bv.x;
                o.y = acc[nt][half * 2 + 1] + bv.y;
                *(float2*)(g_h + (size_t)gr * 64 + gc) = o;
                *(__half2*)(g_h16 + (size_t)gr * 64 + gc) = __floats2half2_rn(o.x, o.y);
            }
        }
    }
}

// ---------------------------------------------------------------- layer GEMM
__global__ __launch_bounds__(256) void gemm_layer_mma(const float* __restrict__ Wl,
                                                      const float* __restrict__ Wr,
                                                      const float* __restrict__ bl) {
    __shared__ __align__(16) __half2 Ah[64 * A2W], Al[64 * A2W];
    __shared__ __align__(16) __half2 Bh[32 * B2W], Bl[32 * B2W];
    int tid = threadIdx.x;
    int wid = tid >> 5, lane = tid & 31;
    int warpM = wid & 3, warpN = wid >> 2;
    int qrow = lane >> 2, qcol = lane & 3;
    int row0 = blockIdx.x * 64;
    float acc[4][4];
#pragma unroll
    for (int nt = 0; nt < 4; nt++)
#pragma unroll
        for (int i = 0; i < 4; i++) acc[nt][i] = 0.f;

#pragma unroll
    for (int c = 0; c < 2; c++) {
        const float* Asrc = c ? g_h : g_agg;
        const float* Bsrc = c ? Wr : Wl;
        float4 va[4], vb[4];
        int k2 = tid >> 3, ng = (tid & 7) * 8;
#pragma unroll
        for (int it = 0; it < 4; it++) {
            int idx = tid + it * 256;
            int r = idx >> 4, c4 = idx & 15;
            int grow = row0 + r;
            va[it] = (grow < NN) ? *(const float4*)(Asrc + (size_t)grow * 64 + c4 * 4)
                                 : make_float4(0.f, 0.f, 0.f, 0.f);
        }
        vb[0] = *(const float4*)(Bsrc + (size_t)(2 * k2) * 64 + ng);
        vb[1] = *(const float4*)(Bsrc + (size_t)(2 * k2) * 64 + ng + 4);
        vb[2] = *(const float4*)(Bsrc + (size_t)(2 * k2 + 1) * 64 + ng);
        vb[3] = *(const float4*)(Bsrc + (size_t)(2 * k2 + 1) * 64 + ng + 4);
        storeA_planes(Ah, Al, va, tid);
        storeB_planes(Bh, Bl, vb, tid);
        __syncthreads();
#pragma unroll
        for (int kk = 0; kk < 4; kk++)
            mma_kstep16(Ah, Al, Bh, Bl, warpM * 16, warpN * 32, kk * 8, qrow, qcol, acc);
        __syncthreads();
    }
#pragma unroll
    for (int nt = 0; nt < 4; nt++) {
        int gc = warpN * 32 + nt * 8 + qcol * 2;
        float2 bv = *(const float2*)(bl + gc);
#pragma unroll
        for (int half = 0; half < 2; half++) {
            int gr = row0 + warpM * 16 + qrow + half * 8;
            if (gr < NN) {
                float2 old = *(const float2*)(g_h + (size_t)gr * 64 + gc);
                float2 o;
                o.x = old.x + fmaxf(acc[nt][half * 2 + 0] + bv.x, 0.f);
                o.y = old.y + fmaxf(acc[nt][half * 2 + 1] + bv.y, 0.f);
                *(float2*)(g_h + (size_t)gr * 64 + gc) = o;
                *(__half2*)(g_h16 + (size_t)gr * 64 + gc) = __floats2half2_rn(o.x, o.y);
            }
        }
    }
}

// ---------------------------------------------------------------- output GEMM
__global__ __launch_bounds__(256) void gemm_out_mma(const float* __restrict__ Wout,
                                                    const float* __restrict__ bout,
                                                    float* __restrict__ out) {
    __shared__ __align__(16) __half2 Ah[64 * A2W], Al[64 * A2W];
    __shared__ __align__(16) __half2 Bh[32 * B2W], Bl[32 * B2W];
    int tid = threadIdx.x;
    int wid = tid >> 5, lane = tid & 31;
    int warpM = wid & 3, warpN = wid >> 2;
    int qrow = lane >> 2, qcol = lane & 3;
    int row0 = blockIdx.x * 64;
    int col0 = blockIdx.y * 64;
    float acc[4][4];
#pragma unroll
    for (int nt = 0; nt < 4; nt++)
#pragma unroll
        for (int i = 0; i < 4; i++) acc[nt][i] = 0.f;

    {
        float4 va[4], vb[4];
        int k2 = tid >> 3, ng = (tid & 7) * 8;
#pragma unroll
        for (int it = 0; it < 4; it++) {
            int idx = tid + it * 256;
            int r = idx >> 4, c4 = idx & 15;
            int grow = row0 + r;
            va[it] = (grow < NN) ? *(const float4*)(g_h + (size_t)grow * 64 + c4 * 4)
                                 : make_float4(0.f, 0.f, 0.f, 0.f);
        }
        vb[0] = *(const float4*)(Wout + (size_t)(2 * k2) * 256 + col0 + ng);
        vb[1] = *(const float4*)(Wout + (size_t)(2 * k2) * 256 + col0 + ng + 4);
        vb[2] = *(const float4*)(Wout + (size_t)(2 * k2 + 1) * 256 + col0 + ng);
        vb[3] = *(const float4*)(Wout + (size_t)(2 * k2 + 1) * 256 + col0 + ng + 4);
        storeA_planes(Ah, Al, va, tid);
        storeB_planes(Bh, Bl, vb, tid);
    }
    __syncthreads();
#pragma unroll
    for (int kk = 0; kk < 4; kk++)
        mma_kstep16(Ah, Al, Bh, Bl, warpM * 16, warpN * 32, kk * 8, qrow, qcol, acc);

#pragma unroll
    for (int nt = 0; nt < 4; nt++) {
        int gc = warpN * 32 + nt * 8 + qcol * 2;
        float2 bv = *(const float2*)(bout + col0 + gc);
#pragma unroll
        for (int half = 0; half < 2; half++) {
            int gr = row0 + warpM * 16 + qrow + half * 8;
            if (gr < NN) {
                float2 o;
                o.x = acc[nt][half * 2 + 0] + bv.x;
                o.y = acc[nt][half * 2 + 1] + bv.y;
                *(float2*)(out + (size_t)gr * 256 + col0 + gc) = o;
            }
        }
    }
}

// ---------------------------------------------------------------- launch
// Fork/join: CSR build (side stream) overlaps gemm_in (main stream).
// Stream/event handles are created once on the first (uncaptured) call and
// reused thereafter; the GPU work launched is identical on every call.
extern "C" void kernel_launch(void* const* d_in, const int* in_sizes, int n_in,
                              void* d_out, int out_size) {
    const float* x    = (const float*)d_in[0];
    const void*  ei   = d_in[1];
    const float* Win  = (const float*)d_in[2];
    const float* bin  = (const float*)d_in[3];
    const float* Wl   = (const float*)d_in[4];
    const float* bl   = (const float*)d_in[5];
    const float* Wr   = (const float*)d_in[6];
    const float* Wout = (const float*)d_in[7];
    const float* bout = (const float*)d_in[8];
    float* out = (float*)d_out;
    int E = in_sizes[1] / 2;

    static cudaStream_t s_side = nullptr;
    static cudaEvent_t  e_fork = nullptr, e_join = nullptr;
    if (s_side == nullptr) {
        cudaStreamCreateWithFlags(&s_side, cudaStreamNonBlocking);
        cudaEventCreateWithFlags(&e_fork, cudaEventDisableTiming);
        cudaEventCreateWithFlags(&e_join, cudaEventDisableTiming);
    }

    // fork: side stream inherits capture dependency from the main stream
    cudaEventRecord(e_fork, 0);
    cudaStreamWaitEvent(s_side, e_fork, 0);

    // ---- side stream: CSR build chain (edge_index only)
    detect_kernel<<<1, 32, 0, s_side>>>((const int*)ei);
    zero_kernel<<<(NN + 255) / 256, 256, 0, s_side>>>();
    degree_kernel<<<(E + 255) / 256, 256, 0, s_side>>>(ei, E);
    scan_partial_kernel<<<NBLK, 1024, 0, s_side>>>();
    scan_bsum_kernel<<<1, 128, 0, s_side>>>();
    scan_add_kernel<<<NBLK, 1024, 0, s_side>>>();
    scatter_kernel<<<(E + 255) / 256, 256, 0, s_side>>>(ei, E);
    cudaEventRecord(e_join, s_side);

    // ---- main stream: input GEMM (x, Win only) — overlaps CSR build
    gemm_in_mma<<<MBLK, 256>>>(x, Win, bin);

    // join: aggregates need both CSR and g_h16
    cudaStreamWaitEvent(0, e_join, 0);

    for (int i = 0; i < 4; i++) {
        aggregate_kernel<<<(NN * 32 + 255) / 256, 256>>>();
        gemm_layer_mma<<<MBLK, 256>>>(Wl + i * HD * HD, Wr + i * HD * HD, bl + i * HD);
    }

    gemm_out_mma<<<dim3(MBLK, 4), 256>>>(Wout, bout, out);
}